// round 8
// baseline (speedup 1.0000x reference)
#include <cuda_runtime.h>
#include <cuda_fp16.h>

#define N_NODES   100000
#define N_EDGES   1600000
#define N_GRAPHS  5000
#define ND        16
#define ED        16
#define HID       20
#define H2        10
#define HP        (HID/2)
#define H2P       (H2/2)
#define PH_STRIDE 32        // half stride per pa/pb row: 32 halves = 64B
#define EHALF     (N_EDGES/2)

// Scratch
__device__ float g_x [N_NODES * HID];
__device__ __align__(128) __half g_pa[N_NODES * PH_STRIDE];
__device__ __align__(128) __half g_pb[N_NODES * PH_STRIDE];
__device__ float g_g [N_GRAPHS * H2];

// ---- packed f32x2 helpers -------------------------------------------------
__device__ __forceinline__ unsigned long long fma2(unsigned long long a,
                                                   unsigned long long b,
                                                   unsigned long long c) {
    unsigned long long d;
    asm("fma.rn.f32x2 %0, %1, %2, %3;" : "=l"(d) : "l"(a), "l"(b), "l"(c));
    return d;
}
__device__ __forceinline__ unsigned long long bcast2(float x) {
    unsigned long long d;
    asm("mov.b64 %0, {%1, %1};" : "=l"(d) : "f"(x));
    return d;
}
__device__ __forceinline__ float2 unpack2(unsigned long long v) {
    float2 r;
    asm("mov.b64 {%0, %1}, %2;" : "=f"(r.x), "=f"(r.y) : "l"(v));
    return r;
}
__device__ __forceinline__ float2 h2f2(unsigned int h) {
    return __half22float2(*(const __half2*)&h);
}

// 256-bit load (Blackwell)
__device__ __forceinline__ void ldg256(const void* p, float r[8]) {
    asm("ld.global.nc.v8.f32 {%0,%1,%2,%3,%4,%5,%6,%7}, [%8];"
        : "=f"(r[0]), "=f"(r[1]), "=f"(r[2]), "=f"(r[3]),
          "=f"(r[4]), "=f"(r[5]), "=f"(r[6]), "=f"(r[7])
        : "l"(p));
}
__device__ __forceinline__ float2 ldg64(const void* p) {
    float2 r;
    asm("ld.global.nc.v2.f32 {%0,%1}, [%2];" : "=f"(r.x), "=f"(r.y) : "l"(p));
    return r;
}

// ---------------------------------------------------------------------------
// Kernel 1: per-node projections pa = A@Wa, pb = A@Wb  (fp16 out, + zeroing)
// ---------------------------------------------------------------------------
__global__ void node_proj_kernel(const float* __restrict__ node_attr,
                                 const float* __restrict__ W_msg) {
    __shared__ __align__(8) float sWa[ND * HID];
    __shared__ __align__(8) float sWb[ND * HID];
    for (int i = threadIdx.x; i < ND * HID; i += blockDim.x) {
        sWa[i] = W_msg[i];
        sWb[i] = W_msg[ND * HID + i];
    }
    __syncthreads();
    const unsigned long long* wa2 = (const unsigned long long*)sWa;
    const unsigned long long* wb2 = (const unsigned long long*)sWb;

    int n = blockIdx.x * blockDim.x + threadIdx.x;

    if (n < (N_GRAPHS * H2) / 4)
        ((float4*)g_g)[n] = make_float4(0.f, 0.f, 0.f, 0.f);

    if (n >= N_NODES) return;

    {
        const float4 z = make_float4(0.f, 0.f, 0.f, 0.f);
        float4* xr = (float4*)(g_x + (size_t)n * HID);
#pragma unroll
        for (int q = 0; q < 5; q++) xr[q] = z;
    }

    float a[ND];
    const float4* ap = (const float4*)(node_attr + (size_t)n * ND);
#pragma unroll
    for (int q = 0; q < 4; q++) {
        float4 v = ap[q];
        a[4*q+0] = v.x; a[4*q+1] = v.y; a[4*q+2] = v.z; a[4*q+3] = v.w;
    }

    unsigned long long acc[HP];
    unsigned int u[HP];

    // pa
#pragma unroll
    for (int p = 0; p < HP; p++) acc[p] = 0ull;
#pragma unroll
    for (int k = 0; k < ND; k++) {
        unsigned long long ak = bcast2(a[k]);
#pragma unroll
        for (int p = 0; p < HP; p++) acc[p] = fma2(ak, wa2[k * HP + p], acc[p]);
    }
#pragma unroll
    for (int p = 0; p < HP; p++) {
        float2 t = unpack2(acc[p]);
        __half2 h = __float22half2_rn(t);
        u[p] = *(unsigned int*)&h;
    }
    {
        char* row = (char*)(g_pa + (size_t)n * PH_STRIDE);
        *(uint4*)(row +  0) = make_uint4(u[0], u[1], u[2], u[3]);
        *(uint4*)(row + 16) = make_uint4(u[4], u[5], u[6], u[7]);
        *(uint2*)(row + 32) = make_uint2(u[8], u[9]);
    }

    // pb
#pragma unroll
    for (int p = 0; p < HP; p++) acc[p] = 0ull;
#pragma unroll
    for (int k = 0; k < ND; k++) {
        unsigned long long ak = bcast2(a[k]);
#pragma unroll
        for (int p = 0; p < HP; p++) acc[p] = fma2(ak, wb2[k * HP + p], acc[p]);
    }
#pragma unroll
    for (int p = 0; p < HP; p++) {
        float2 t = unpack2(acc[p]);
        __half2 h = __float22half2_rn(t);
        u[p] = *(unsigned int*)&h;
    }
    {
        char* row = (char*)(g_pb + (size_t)n * PH_STRIDE);
        *(uint4*)(row +  0) = make_uint4(u[0], u[1], u[2], u[3]);
        *(uint4*)(row + 16) = make_uint4(u[4], u[5], u[6], u[7]);
        *(uint2*)(row + 32) = make_uint2(u[8], u[9]);
    }
}

// ---------------------------------------------------------------------------
// Kernel 2: edge message + scatter-sum. 2 edges/thread, all loads batched
// up-front for deep MLP. e0 = t, e1 = t + N_EDGES/2 (both streams coalesced).
// ---------------------------------------------------------------------------
__global__ __launch_bounds__(256) void edge_kernel(
        const int*   __restrict__ edge_index,
        const float* __restrict__ edge_attr,
        const float* __restrict__ W_msg,
        const float* __restrict__ b_msg) {
    __shared__ __align__(8) float sWe[ED * HID];
    __shared__ __align__(8) float sb[HID];
    for (int i = threadIdx.x; i < ED * HID; i += blockDim.x)
        sWe[i] = W_msg[2 * ND * HID + i];
    for (int i = threadIdx.x; i < HID; i += blockDim.x)
        sb[i] = b_msg[i];
    __syncthreads();
    const unsigned long long* we2 = (const unsigned long long*)sWe;
    const unsigned long long* sb2 = (const unsigned long long*)sb;

    int t = blockIdx.x * blockDim.x + threadIdx.x;
    if (t >= EHALF) return;
    int e0 = t;
    int e1 = t + EHALF;

    // all 4 indices first
    int src0 = __ldg(edge_index + e0);
    int src1 = __ldg(edge_index + e1);
    int dst0 = __ldg(edge_index + N_EDGES + e0);
    int dst1 = __ldg(edge_index + N_EDGES + e1);

    // all 8 gathers issued back-to-back (deep LSU queue)
    const char* par0 = (const char*)(g_pa + (size_t)src0 * PH_STRIDE);
    const char* pbr0 = (const char*)(g_pb + (size_t)dst0 * PH_STRIDE);
    const char* par1 = (const char*)(g_pa + (size_t)src1 * PH_STRIDE);
    const char* pbr1 = (const char*)(g_pb + (size_t)dst1 * PH_STRIDE);
    float A0[8], B0[8], A1[8], B1[8];
    ldg256(par0, A0);
    ldg256(pbr0, B0);
    ldg256(par1, A1);
    ldg256(pbr1, B1);
    float2 a0t = ldg64(par0 + 32);
    float2 b0t = ldg64(pbr0 + 32);
    float2 a1t = ldg64(par1 + 32);
    float2 b1t = ldg64(pbr1 + 32);

    // both edge_attr rows
    float ea0[ED], ea1[ED];
    ldg256(edge_attr + (size_t)e0 * ED,     ea0);
    ldg256(edge_attr + (size_t)e0 * ED + 8, ea0 + 8);
    ldg256(edge_attr + (size_t)e1 * ED,     ea1);
    ldg256(edge_attr + (size_t)e1 * ED + 8, ea1 + 8);

    // ---- edge 0 ----
    {
        unsigned long long acc[HP];
#pragma unroll
        for (int p = 0; p < HP; p++) acc[p] = sb2[p];
#pragma unroll
        for (int k = 0; k < ED; k++) {
            unsigned long long b = bcast2(ea0[k]);
#pragma unroll
            for (int p = 0; p < HP; p++)
                acc[p] = fma2(b, we2[k * HP + p], acc[p]);
        }
        unsigned int au[HP] = {
            __float_as_uint(A0[0]), __float_as_uint(A0[1]), __float_as_uint(A0[2]),
            __float_as_uint(A0[3]), __float_as_uint(A0[4]), __float_as_uint(A0[5]),
            __float_as_uint(A0[6]), __float_as_uint(A0[7]),
            __float_as_uint(a0t.x), __float_as_uint(a0t.y)};
        unsigned int bu[HP] = {
            __float_as_uint(B0[0]), __float_as_uint(B0[1]), __float_as_uint(B0[2]),
            __float_as_uint(B0[3]), __float_as_uint(B0[4]), __float_as_uint(B0[5]),
            __float_as_uint(B0[6]), __float_as_uint(B0[7]),
            __float_as_uint(b0t.x), __float_as_uint(b0t.y)};
        float m[HID];
#pragma unroll
        for (int p = 0; p < HP; p++) {
            float2 c = unpack2(acc[p]);
            float2 fa = h2f2(au[p]);
            float2 fb = h2f2(bu[p]);
            m[2*p]   = fmaxf(c.x + fa.x + fb.x, 0.f);
            m[2*p+1] = fmaxf(c.y + fa.y + fb.y, 0.f);
        }
        float* xr = g_x + (size_t)dst0 * HID;
#pragma unroll
        for (int q = 0; q < 5; q++) {
            asm volatile("red.global.add.v4.f32 [%0], {%1,%2,%3,%4};"
                         :: "l"(xr + 4*q),
                            "f"(m[4*q]), "f"(m[4*q+1]), "f"(m[4*q+2]), "f"(m[4*q+3])
                         : "memory");
        }
    }

    // ---- edge 1 ----
    {
        unsigned long long acc[HP];
#pragma unroll
        for (int p = 0; p < HP; p++) acc[p] = sb2[p];
#pragma unroll
        for (int k = 0; k < ED; k++) {
            unsigned long long b = bcast2(ea1[k]);
#pragma unroll
            for (int p = 0; p < HP; p++)
                acc[p] = fma2(b, we2[k * HP + p], acc[p]);
        }
        unsigned int au[HP] = {
            __float_as_uint(A1[0]), __float_as_uint(A1[1]), __float_as_uint(A1[2]),
            __float_as_uint(A1[3]), __float_as_uint(A1[4]), __float_as_uint(A1[5]),
            __float_as_uint(A1[6]), __float_as_uint(A1[7]),
            __float_as_uint(a1t.x), __float_as_uint(a1t.y)};
        unsigned int bu[HP] = {
            __float_as_uint(B1[0]), __float_as_uint(B1[1]), __float_as_uint(B1[2]),
            __float_as_uint(B1[3]), __float_as_uint(B1[4]), __float_as_uint(B1[5]),
            __float_as_uint(B1[6]), __float_as_uint(B1[7]),
            __float_as_uint(b1t.x), __float_as_uint(b1t.y)};
        float m[HID];
#pragma unroll
        for (int p = 0; p < HP; p++) {
            float2 c = unpack2(acc[p]);
            float2 fa = h2f2(au[p]);
            float2 fb = h2f2(bu[p]);
            m[2*p]   = fmaxf(c.x + fa.x + fb.x, 0.f);
            m[2*p+1] = fmaxf(c.y + fa.y + fb.y, 0.f);
        }
        float* xr = g_x + (size_t)dst1 * HID;
#pragma unroll
        for (int q = 0; q < 5; q++) {
            asm volatile("red.global.add.v4.f32 [%0], {%1,%2,%3,%4};"
                         :: "l"(xr + 4*q),
                            "f"(m[4*q]), "f"(m[4*q+1]), "f"(m[4*q+2]), "f"(m[4*q+3])
                         : "memory");
        }
    }
}

// ---------------------------------------------------------------------------
// Kernel 3: node MLP + graph pooling
// ---------------------------------------------------------------------------
__global__ __launch_bounds__(256) void node_mlp_kernel(
        const int*   __restrict__ batch,
        const float* __restrict__ W1,
        const float* __restrict__ b1) {
    __shared__ __align__(8) float sW[HID * H2];
    __shared__ __align__(8) float sb[H2];
    for (int i = threadIdx.x; i < HID * H2; i += blockDim.x) sW[i] = W1[i];
    for (int i = threadIdx.x; i < H2; i += blockDim.x) sb[i] = b1[i];
    __syncthreads();
    const unsigned long long* w2 = (const unsigned long long*)sW;
    const unsigned long long* sb2 = (const unsigned long long*)sb;

    int n = blockIdx.x * blockDim.x + threadIdx.x;
    if (n >= N_NODES) return;

    int b = __ldg(batch + n);

    float x[HID];
    const float4* xp = (const float4*)(g_x + (size_t)n * HID);
#pragma unroll
    for (int q = 0; q < 5; q++) {
        float4 v = xp[q];
        x[4*q+0] = v.x; x[4*q+1] = v.y; x[4*q+2] = v.z; x[4*q+3] = v.w;
    }

    unsigned long long acc[H2P];
#pragma unroll
    for (int p = 0; p < H2P; p++) acc[p] = sb2[p];
#pragma unroll
    for (int k = 0; k < HID; k++) {
        unsigned long long xk = bcast2(x[k]);
#pragma unroll
        for (int p = 0; p < H2P; p++) acc[p] = fma2(xk, w2[k * H2P + p], acc[p]);
    }

    float y[H2];
#pragma unroll
    for (int p = 0; p < H2P; p++) {
        float2 t = unpack2(acc[p]);
        y[2*p]   = fmaxf(t.x, 0.f);
        y[2*p+1] = fmaxf(t.y, 0.f);
    }

    float* gr = g_g + (size_t)b * H2;
#pragma unroll
    for (int q = 0; q < 5; q++) {
        asm volatile("red.global.add.v2.f32 [%0], {%1,%2};"
                     :: "l"(gr + 2*q), "f"(y[2*q]), "f"(y[2*q+1])
                     : "memory");
    }
}

// ---------------------------------------------------------------------------
// Kernel 4: graph MLP
// ---------------------------------------------------------------------------
__global__ __launch_bounds__(256) void graph_mlp_kernel(
        const float* __restrict__ W2,
        const float* __restrict__ b2,
        const float* __restrict__ W3,
        const float* __restrict__ b3,
        float* __restrict__ out) {
    __shared__ float sW2[H2 * H2];
    __shared__ float sb2[H2];
    __shared__ float sW3[H2];
    __shared__ float sb3;
    for (int i = threadIdx.x; i < H2 * H2; i += blockDim.x) sW2[i] = W2[i];
    if (threadIdx.x < H2) { sb2[threadIdx.x] = b2[threadIdx.x]; sW3[threadIdx.x] = W3[threadIdx.x]; }
    if (threadIdx.x == 0) sb3 = b3[0];
    __syncthreads();

    int g = blockIdx.x * blockDim.x + threadIdx.x;
    if (g >= N_GRAPHS) return;

    float v[H2];
    const float2* gp = (const float2*)(g_g + (size_t)g * H2);
#pragma unroll
    for (int q = 0; q < 5; q++) {
        float2 t = gp[q];
        v[2*q] = t.x; v[2*q+1] = t.y;
    }

    float o = sb3;
#pragma unroll
    for (int j = 0; j < H2; j++) {
        float h = sb2[j];
#pragma unroll
        for (int k = 0; k < H2; k++) h = fmaf(v[k], sW2[k * H2 + j], h);
        o = fmaf(fmaxf(h, 0.f), sW3[j], o);
    }
    out[g] = o;
}

// ---------------------------------------------------------------------------
extern "C" void kernel_launch(void* const* d_in, const int* in_sizes, int n_in,
                              void* d_out, int out_size) {
    const int*   edge_index = (const int*)  d_in[0];
    const float* node_attr  = (const float*)d_in[1];
    const float* edge_attr  = (const float*)d_in[2];
    const int*   batch      = (const int*)  d_in[3];
    const float* W_msg      = (const float*)d_in[4];
    const float* b_msg      = (const float*)d_in[5];
    const float* W1         = (const float*)d_in[6];
    const float* b1         = (const float*)d_in[7];
    const float* W2         = (const float*)d_in[8];
    const float* b2         = (const float*)d_in[9];
    const float* W3         = (const float*)d_in[10];
    const float* b3         = (const float*)d_in[11];
    float* out = (float*)d_out;

    node_proj_kernel<<<(N_NODES + 255) / 256, 256>>>(node_attr, W_msg);
    edge_kernel<<<(EHALF + 255) / 256, 256>>>(edge_index, edge_attr, W_msg, b_msg);
    node_mlp_kernel<<<(N_NODES + 255) / 256, 256>>>(batch, W1, b1);
    graph_mlp_kernel<<<(N_GRAPHS + 255) / 256, 256>>>(W2, b2, W3, b3, out);
}

// round 9
// speedup vs baseline: 1.4584x; 1.4584x over previous
#include <cuda_runtime.h>
#include <cuda_fp16.h>

#define N_NODES   100000
#define N_EDGES   1600000
#define N_GRAPHS  5000
#define ND        16
#define ED        16
#define HID       20
#define H2        10
#define HP        (HID/2)
#define H2P       (H2/2)
#define PH_STRIDE 32        // half stride per pa/pb row: 32 halves = 64B

// Scratch
__device__ float g_x [N_NODES * HID];
__device__ __align__(128) __half g_pa[N_NODES * PH_STRIDE];
__device__ __align__(128) __half g_pb[N_NODES * PH_STRIDE];
__device__ float g_g [N_GRAPHS * H2];
__device__ unsigned int g_done;   // completion counter for last-block epilogue

// ---- packed f32x2 helpers -------------------------------------------------
__device__ __forceinline__ unsigned long long fma2(unsigned long long a,
                                                   unsigned long long b,
                                                   unsigned long long c) {
    unsigned long long d;
    asm("fma.rn.f32x2 %0, %1, %2, %3;" : "=l"(d) : "l"(a), "l"(b), "l"(c));
    return d;
}
__device__ __forceinline__ unsigned long long bcast2(float x) {
    unsigned long long d;
    asm("mov.b64 %0, {%1, %1};" : "=l"(d) : "f"(x));
    return d;
}
__device__ __forceinline__ float2 unpack2(unsigned long long v) {
    float2 r;
    asm("mov.b64 {%0, %1}, %2;" : "=f"(r.x), "=f"(r.y) : "l"(v));
    return r;
}
__device__ __forceinline__ float2 h2f2(unsigned int h) {
    return __half22float2(*(const __half2*)&h);
}

// 256-bit load (Blackwell)
__device__ __forceinline__ void ldg256(const void* p, float r[8]) {
    asm("ld.global.nc.v8.f32 {%0,%1,%2,%3,%4,%5,%6,%7}, [%8];"
        : "=f"(r[0]), "=f"(r[1]), "=f"(r[2]), "=f"(r[3]),
          "=f"(r[4]), "=f"(r[5]), "=f"(r[6]), "=f"(r[7])
        : "l"(p));
}
__device__ __forceinline__ float2 ldg64(const void* p) {
    float2 r;
    asm("ld.global.nc.v2.f32 {%0,%1}, [%2];" : "=f"(r.x), "=f"(r.y) : "l"(p));
    return r;
}

// ---------------------------------------------------------------------------
// Kernel 1: per-node projections pa = A@Wa, pb = A@Wb  (fp16 out, + zeroing)
// ---------------------------------------------------------------------------
__global__ void node_proj_kernel(const float* __restrict__ node_attr,
                                 const float* __restrict__ W_msg) {
    __shared__ __align__(8) float sWa[ND * HID];
    __shared__ __align__(8) float sWb[ND * HID];
    for (int i = threadIdx.x; i < ND * HID; i += blockDim.x) {
        sWa[i] = W_msg[i];
        sWb[i] = W_msg[ND * HID + i];
    }
    __syncthreads();
    const unsigned long long* wa2 = (const unsigned long long*)sWa;
    const unsigned long long* wb2 = (const unsigned long long*)sWb;

    int n = blockIdx.x * blockDim.x + threadIdx.x;

    if (n == 0) g_done = 0;   // reset epilogue counter each replay

    if (n < (N_GRAPHS * H2) / 4)
        ((float4*)g_g)[n] = make_float4(0.f, 0.f, 0.f, 0.f);

    if (n >= N_NODES) return;

    {
        const float4 z = make_float4(0.f, 0.f, 0.f, 0.f);
        float4* xr = (float4*)(g_x + (size_t)n * HID);
#pragma unroll
        for (int q = 0; q < 5; q++) xr[q] = z;
    }

    float a[ND];
    const float4* ap = (const float4*)(node_attr + (size_t)n * ND);
#pragma unroll
    for (int q = 0; q < 4; q++) {
        float4 v = ap[q];
        a[4*q+0] = v.x; a[4*q+1] = v.y; a[4*q+2] = v.z; a[4*q+3] = v.w;
    }

    unsigned long long acc[HP];
    unsigned int u[HP];

    // pa
#pragma unroll
    for (int p = 0; p < HP; p++) acc[p] = 0ull;
#pragma unroll
    for (int k = 0; k < ND; k++) {
        unsigned long long ak = bcast2(a[k]);
#pragma unroll
        for (int p = 0; p < HP; p++) acc[p] = fma2(ak, wa2[k * HP + p], acc[p]);
    }
#pragma unroll
    for (int p = 0; p < HP; p++) {
        float2 t = unpack2(acc[p]);
        __half2 h = __float22half2_rn(t);
        u[p] = *(unsigned int*)&h;
    }
    {
        char* row = (char*)(g_pa + (size_t)n * PH_STRIDE);
        *(uint4*)(row +  0) = make_uint4(u[0], u[1], u[2], u[3]);
        *(uint4*)(row + 16) = make_uint4(u[4], u[5], u[6], u[7]);
        *(uint2*)(row + 32) = make_uint2(u[8], u[9]);
    }

    // pb
#pragma unroll
    for (int p = 0; p < HP; p++) acc[p] = 0ull;
#pragma unroll
    for (int k = 0; k < ND; k++) {
        unsigned long long ak = bcast2(a[k]);
#pragma unroll
        for (int p = 0; p < HP; p++) acc[p] = fma2(ak, wb2[k * HP + p], acc[p]);
    }
#pragma unroll
    for (int p = 0; p < HP; p++) {
        float2 t = unpack2(acc[p]);
        __half2 h = __float22half2_rn(t);
        u[p] = *(unsigned int*)&h;
    }
    {
        char* row = (char*)(g_pb + (size_t)n * PH_STRIDE);
        *(uint4*)(row +  0) = make_uint4(u[0], u[1], u[2], u[3]);
        *(uint4*)(row + 16) = make_uint4(u[4], u[5], u[6], u[7]);
        *(uint2*)(row + 32) = make_uint2(u[8], u[9]);
    }
}

// ---------------------------------------------------------------------------
// Kernel 2: edge message + scatter-sum (exact R6 hot path: v8 loads)
// ---------------------------------------------------------------------------
__global__ __launch_bounds__(256) void edge_kernel(
        const int*   __restrict__ edge_index,
        const float* __restrict__ edge_attr,
        const float* __restrict__ W_msg,
        const float* __restrict__ b_msg) {
    __shared__ __align__(8) float sWe[ED * HID];
    __shared__ __align__(8) float sb[HID];
    for (int i = threadIdx.x; i < ED * HID; i += blockDim.x)
        sWe[i] = W_msg[2 * ND * HID + i];
    for (int i = threadIdx.x; i < HID; i += blockDim.x)
        sb[i] = b_msg[i];
    __syncthreads();
    const unsigned long long* we2 = (const unsigned long long*)sWe;
    const unsigned long long* sb2 = (const unsigned long long*)sb;

    int e = blockIdx.x * blockDim.x + threadIdx.x;
    if (e >= N_EDGES) return;

    int src = __ldg(edge_index + e);
    int dst = __ldg(edge_index + N_EDGES + e);

    const char* par = (const char*)(g_pa + (size_t)src * PH_STRIDE);
    const char* pbr = (const char*)(g_pb + (size_t)dst * PH_STRIDE);
    float A8[8], B8[8];
    ldg256(par, A8);
    float2 A2 = ldg64(par + 32);
    ldg256(pbr, B8);
    float2 B2 = ldg64(pbr + 32);

    float ea[ED];
    ldg256(edge_attr + (size_t)e * ED, ea);
    ldg256(edge_attr + (size_t)e * ED + 8, ea + 8);

    unsigned long long acc[HP];
#pragma unroll
    for (int p = 0; p < HP; p++) acc[p] = sb2[p];

#pragma unroll
    for (int k = 0; k < ED; k++) {
        unsigned long long b = bcast2(ea[k]);
#pragma unroll
        for (int p = 0; p < HP; p++)
            acc[p] = fma2(b, we2[k * HP + p], acc[p]);
    }

    unsigned int au[HP] = {
        __float_as_uint(A8[0]), __float_as_uint(A8[1]), __float_as_uint(A8[2]),
        __float_as_uint(A8[3]), __float_as_uint(A8[4]), __float_as_uint(A8[5]),
        __float_as_uint(A8[6]), __float_as_uint(A8[7]),
        __float_as_uint(A2.x),  __float_as_uint(A2.y)};
    unsigned int bu[HP] = {
        __float_as_uint(B8[0]), __float_as_uint(B8[1]), __float_as_uint(B8[2]),
        __float_as_uint(B8[3]), __float_as_uint(B8[4]), __float_as_uint(B8[5]),
        __float_as_uint(B8[6]), __float_as_uint(B8[7]),
        __float_as_uint(B2.x),  __float_as_uint(B2.y)};

    float m[HID];
#pragma unroll
    for (int p = 0; p < HP; p++) {
        float2 c = unpack2(acc[p]);
        float2 fa = h2f2(au[p]);
        float2 fb = h2f2(bu[p]);
        m[2*p]   = fmaxf(c.x + fa.x + fb.x, 0.f);
        m[2*p+1] = fmaxf(c.y + fa.y + fb.y, 0.f);
    }

    float* xr = g_x + (size_t)dst * HID;
#pragma unroll
    for (int q = 0; q < 5; q++) {
        asm volatile("red.global.add.v4.f32 [%0], {%1,%2,%3,%4};"
                     :: "l"(xr + 4*q),
                        "f"(m[4*q]), "f"(m[4*q+1]), "f"(m[4*q+2]), "f"(m[4*q+3])
                     : "memory");
    }
}

// ---------------------------------------------------------------------------
// Kernel 3: node MLP + pooling, with fused graph-MLP epilogue in last block
// ---------------------------------------------------------------------------
__global__ __launch_bounds__(256) void node_mlp_kernel(
        const int*   __restrict__ batch,
        const float* __restrict__ W1,
        const float* __restrict__ b1,
        const float* __restrict__ W2,
        const float* __restrict__ b2,
        const float* __restrict__ W3,
        const float* __restrict__ b3,
        float* __restrict__ out) {
    __shared__ __align__(8) float sW[HID * H2];
    __shared__ __align__(8) float sb[H2];
    __shared__ unsigned int sIsLast;
    for (int i = threadIdx.x; i < HID * H2; i += blockDim.x) sW[i] = W1[i];
    for (int i = threadIdx.x; i < H2; i += blockDim.x) sb[i] = b1[i];
    __syncthreads();
    const unsigned long long* w2 = (const unsigned long long*)sW;
    const unsigned long long* sb2 = (const unsigned long long*)sb;

    int n = blockIdx.x * blockDim.x + threadIdx.x;
    if (n < N_NODES) {
        int b = __ldg(batch + n);

        float x[HID];
        const float4* xp = (const float4*)(g_x + (size_t)n * HID);
#pragma unroll
        for (int q = 0; q < 5; q++) {
            float4 v = xp[q];
            x[4*q+0] = v.x; x[4*q+1] = v.y; x[4*q+2] = v.z; x[4*q+3] = v.w;
        }

        unsigned long long acc[H2P];
#pragma unroll
        for (int p = 0; p < H2P; p++) acc[p] = sb2[p];
#pragma unroll
        for (int k = 0; k < HID; k++) {
            unsigned long long xk = bcast2(x[k]);
#pragma unroll
            for (int p = 0; p < H2P; p++) acc[p] = fma2(xk, w2[k * H2P + p], acc[p]);
        }

        float y[H2];
#pragma unroll
        for (int p = 0; p < H2P; p++) {
            float2 t = unpack2(acc[p]);
            y[2*p]   = fmaxf(t.x, 0.f);
            y[2*p+1] = fmaxf(t.y, 0.f);
        }

        float* gr = g_g + (size_t)b * H2;
#pragma unroll
        for (int q = 0; q < 5; q++) {
            asm volatile("red.global.add.v2.f32 [%0], {%1,%2};"
                         :: "l"(gr + 2*q), "f"(y[2*q]), "f"(y[2*q+1])
                         : "memory");
        }
    }

    // ---- last-block epilogue: graph MLP ----
    __syncthreads();                 // all block's reductions issued
    if (threadIdx.x == 0) {
        __threadfence();             // make this block's red ops visible
        unsigned int prev = atomicAdd(&g_done, 1u);
        sIsLast = (prev == gridDim.x - 1) ? 1u : 0u;
    }
    __syncthreads();
    if (!sIsLast) return;
    __threadfence();                 // acquire: see all other blocks' red ops

    // reuse shared for W2 etc.
    __shared__ float sW2[H2 * H2];
    __shared__ float sb2e[H2];
    __shared__ float sW3[H2];
    __shared__ float sb3;
    for (int i = threadIdx.x; i < H2 * H2; i += blockDim.x) sW2[i] = W2[i];
    if (threadIdx.x < H2) { sb2e[threadIdx.x] = b2[threadIdx.x]; sW3[threadIdx.x] = W3[threadIdx.x]; }
    if (threadIdx.x == 0) sb3 = b3[0];
    __syncthreads();

    for (int g = threadIdx.x; g < N_GRAPHS; g += blockDim.x) {
        float v[H2];
        const float2* gp = (const float2*)(g_g + (size_t)g * H2);
#pragma unroll
        for (int q = 0; q < 5; q++) {
            float2 t = gp[q];
            v[2*q] = t.x; v[2*q+1] = t.y;
        }
        float o = sb3;
#pragma unroll
        for (int j = 0; j < H2; j++) {
            float h = sb2e[j];
#pragma unroll
            for (int k = 0; k < H2; k++) h = fmaf(v[k], sW2[k * H2 + j], h);
            o = fmaf(fmaxf(h, 0.f), sW3[j], o);
        }
        out[g] = o;
    }
}

// ---------------------------------------------------------------------------
extern "C" void kernel_launch(void* const* d_in, const int* in_sizes, int n_in,
                              void* d_out, int out_size) {
    const int*   edge_index = (const int*)  d_in[0];
    const float* node_attr  = (const float*)d_in[1];
    const float* edge_attr  = (const float*)d_in[2];
    const int*   batch      = (const int*)  d_in[3];
    const float* W_msg      = (const float*)d_in[4];
    const float* b_msg      = (const float*)d_in[5];
    const float* W1         = (const float*)d_in[6];
    const float* b1         = (const float*)d_in[7];
    const float* W2         = (const float*)d_in[8];
    const float* b2         = (const float*)d_in[9];
    const float* W3         = (const float*)d_in[10];
    const float* b3         = (const float*)d_in[11];
    float* out = (float*)d_out;

    node_proj_kernel<<<(N_NODES + 255) / 256, 256>>>(node_attr, W_msg);
    edge_kernel<<<(N_EDGES + 255) / 256, 256>>>(edge_index, edge_attr, W_msg, b_msg);
    node_mlp_kernel<<<(N_NODES + 255) / 256, 256>>>(batch, W1, b1, W2, b2, W3, b3, out);
}

// round 10
// speedup vs baseline: 1.6122x; 1.1054x over previous
#include <cuda_runtime.h>
#include <cuda_fp16.h>

#define N_NODES   100000
#define N_EDGES   1600000
#define N_GRAPHS  5000
#define ND        16
#define ED        16
#define HID       20
#define H2        10
#define HP        (HID/2)
#define H2P       (H2/2)
#define PH_STRIDE 32        // half stride per pa/pb row: 32 halves = 64B
#define NPB       ((N_NODES + 255) / 256)   // node blocks (391)

// Scratch
__device__ float g_x [N_NODES * HID];
__device__ __align__(128) __half g_pa[N_NODES * PH_STRIDE];
__device__ __align__(128) __half g_pb[N_NODES * PH_STRIDE];
__device__ float g_g [N_GRAPHS * H2];

// ---- packed f32x2 helpers -------------------------------------------------
__device__ __forceinline__ unsigned long long fma2(unsigned long long a,
                                                   unsigned long long b,
                                                   unsigned long long c) {
    unsigned long long d;
    asm("fma.rn.f32x2 %0, %1, %2, %3;" : "=l"(d) : "l"(a), "l"(b), "l"(c));
    return d;
}
__device__ __forceinline__ unsigned long long bcast2(float x) {
    unsigned long long d;
    asm("mov.b64 %0, {%1, %1};" : "=l"(d) : "f"(x));
    return d;
}
__device__ __forceinline__ float2 unpack2(unsigned long long v) {
    float2 r;
    asm("mov.b64 {%0, %1}, %2;" : "=f"(r.x), "=f"(r.y) : "l"(v));
    return r;
}
__device__ __forceinline__ float2 h2f2(unsigned int h) {
    return __half22float2(*(const __half2*)&h);
}

// 256-bit load (Blackwell)
__device__ __forceinline__ void ldg256(const void* p, float r[8]) {
    asm("ld.global.nc.v8.f32 {%0,%1,%2,%3,%4,%5,%6,%7}, [%8];"
        : "=f"(r[0]), "=f"(r[1]), "=f"(r[2]), "=f"(r[3]),
          "=f"(r[4]), "=f"(r[5]), "=f"(r[6]), "=f"(r[7])
        : "l"(p));
}
__device__ __forceinline__ float2 ldg64(const void* p) {
    float2 r;
    asm("ld.global.nc.v2.f32 {%0,%1}, [%2];" : "=f"(r.x), "=f"(r.y) : "l"(p));
    return r;
}

// ---------------------------------------------------------------------------
// Kernel 1: per-node projections, 2-way split grid.
// Blocks [0, NPB)      -> pa = A@Wa  (+ zero g_x row, zero g_g)
// Blocks [NPB, 2*NPB)  -> pb = A@Wb
// ---------------------------------------------------------------------------
__global__ __launch_bounds__(256) void node_proj_kernel(
        const float* __restrict__ node_attr,
        const float* __restrict__ W_msg) {
    const bool is_pb = (blockIdx.x >= NPB);
    __shared__ __align__(8) float sW[ND * HID];
    {
        const float* Wsrc = W_msg + (is_pb ? ND * HID : 0);
        for (int i = threadIdx.x; i < ND * HID; i += blockDim.x)
            sW[i] = Wsrc[i];
    }
    __syncthreads();
    const unsigned long long* w2 = (const unsigned long long*)sW;

    int n = (blockIdx.x - (is_pb ? NPB : 0)) * blockDim.x + threadIdx.x;

    if (!is_pb) {
        // fused zeroing in the pa half only
        if (n < (N_GRAPHS * H2) / 4)
            ((float4*)g_g)[n] = make_float4(0.f, 0.f, 0.f, 0.f);
        if (n < N_NODES) {
            const float4 z = make_float4(0.f, 0.f, 0.f, 0.f);
            float4* xr = (float4*)(g_x + (size_t)n * HID);
#pragma unroll
            for (int q = 0; q < 5; q++) xr[q] = z;
        }
    }

    if (n >= N_NODES) return;

    float a[ND];
    const float4* ap = (const float4*)(node_attr + (size_t)n * ND);
#pragma unroll
    for (int q = 0; q < 4; q++) {
        float4 v = ap[q];
        a[4*q+0] = v.x; a[4*q+1] = v.y; a[4*q+2] = v.z; a[4*q+3] = v.w;
    }

    unsigned long long acc[HP];
#pragma unroll
    for (int p = 0; p < HP; p++) acc[p] = 0ull;
#pragma unroll
    for (int k = 0; k < ND; k++) {
        unsigned long long ak = bcast2(a[k]);
#pragma unroll
        for (int p = 0; p < HP; p++) acc[p] = fma2(ak, w2[k * HP + p], acc[p]);
    }

    unsigned int u[HP];
#pragma unroll
    for (int p = 0; p < HP; p++) {
        float2 t = unpack2(acc[p]);
        __half2 h = __float22half2_rn(t);
        u[p] = *(unsigned int*)&h;
    }
    {
        __half* dstbase = is_pb ? g_pb : g_pa;
        char* row = (char*)(dstbase + (size_t)n * PH_STRIDE);
        *(uint4*)(row +  0) = make_uint4(u[0], u[1], u[2], u[3]);
        *(uint4*)(row + 16) = make_uint4(u[4], u[5], u[6], u[7]);
        *(uint2*)(row + 32) = make_uint2(u[8], u[9]);
    }
}

// ---------------------------------------------------------------------------
// Kernel 2: edge message + scatter-sum (exact R6 hot path)
// ---------------------------------------------------------------------------
__global__ __launch_bounds__(256) void edge_kernel(
        const int*   __restrict__ edge_index,
        const float* __restrict__ edge_attr,
        const float* __restrict__ W_msg,
        const float* __restrict__ b_msg) {
    __shared__ __align__(8) float sWe[ED * HID];
    __shared__ __align__(8) float sb[HID];
    for (int i = threadIdx.x; i < ED * HID; i += blockDim.x)
        sWe[i] = W_msg[2 * ND * HID + i];
    for (int i = threadIdx.x; i < HID; i += blockDim.x)
        sb[i] = b_msg[i];
    __syncthreads();
    const unsigned long long* we2 = (const unsigned long long*)sWe;
    const unsigned long long* sb2 = (const unsigned long long*)sb;

    int e = blockIdx.x * blockDim.x + threadIdx.x;
    if (e >= N_EDGES) return;

    int src = __ldg(edge_index + e);
    int dst = __ldg(edge_index + N_EDGES + e);

    const char* par = (const char*)(g_pa + (size_t)src * PH_STRIDE);
    const char* pbr = (const char*)(g_pb + (size_t)dst * PH_STRIDE);
    float A8[8], B8[8];
    ldg256(par, A8);
    float2 A2 = ldg64(par + 32);
    ldg256(pbr, B8);
    float2 B2 = ldg64(pbr + 32);

    float ea[ED];
    ldg256(edge_attr + (size_t)e * ED, ea);
    ldg256(edge_attr + (size_t)e * ED + 8, ea + 8);

    unsigned long long acc[HP];
#pragma unroll
    for (int p = 0; p < HP; p++) acc[p] = sb2[p];

#pragma unroll
    for (int k = 0; k < ED; k++) {
        unsigned long long b = bcast2(ea[k]);
#pragma unroll
        for (int p = 0; p < HP; p++)
            acc[p] = fma2(b, we2[k * HP + p], acc[p]);
    }

    unsigned int au[HP] = {
        __float_as_uint(A8[0]), __float_as_uint(A8[1]), __float_as_uint(A8[2]),
        __float_as_uint(A8[3]), __float_as_uint(A8[4]), __float_as_uint(A8[5]),
        __float_as_uint(A8[6]), __float_as_uint(A8[7]),
        __float_as_uint(A2.x),  __float_as_uint(A2.y)};
    unsigned int bu[HP] = {
        __float_as_uint(B8[0]), __float_as_uint(B8[1]), __float_as_uint(B8[2]),
        __float_as_uint(B8[3]), __float_as_uint(B8[4]), __float_as_uint(B8[5]),
        __float_as_uint(B8[6]), __float_as_uint(B8[7]),
        __float_as_uint(B2.x),  __float_as_uint(B2.y)};

    float m[HID];
#pragma unroll
    for (int p = 0; p < HP; p++) {
        float2 c = unpack2(acc[p]);
        float2 fa = h2f2(au[p]);
        float2 fb = h2f2(bu[p]);
        m[2*p]   = fmaxf(c.x + fa.x + fb.x, 0.f);
        m[2*p+1] = fmaxf(c.y + fa.y + fb.y, 0.f);
    }

    float* xr = g_x + (size_t)dst * HID;
#pragma unroll
    for (int q = 0; q < 5; q++) {
        asm volatile("red.global.add.v4.f32 [%0], {%1,%2,%3,%4};"
                     :: "l"(xr + 4*q),
                        "f"(m[4*q]), "f"(m[4*q+1]), "f"(m[4*q+2]), "f"(m[4*q+3])
                     : "memory");
    }
}

// ---------------------------------------------------------------------------
// Kernel 3: node MLP + graph pooling, smem-staged g_x reads
// ---------------------------------------------------------------------------
__global__ __launch_bounds__(256) void node_mlp_kernel(
        const int*   __restrict__ batch,
        const float* __restrict__ W1,
        const float* __restrict__ b1) {
    __shared__ __align__(8) float sW[HID * H2];
    __shared__ __align__(8) float sb[H2];
    __shared__ __align__(16) float sx[256 * HID];   // 20 KB
    for (int i = threadIdx.x; i < HID * H2; i += blockDim.x) sW[i] = W1[i];
    for (int i = threadIdx.x; i < H2; i += blockDim.x) sb[i] = b1[i];

    int n0 = blockIdx.x * 256;
    int cnt = N_NODES - n0; if (cnt > 256) cnt = 256;
    {
        const float4* src = (const float4*)(g_x + (size_t)n0 * HID);
        int nf4 = cnt * (HID / 4);   // cnt*5 float4s
        for (int i = threadIdx.x; i < nf4; i += blockDim.x)
            ((float4*)sx)[i] = src[i];
    }
    __syncthreads();
    const unsigned long long* w2 = (const unsigned long long*)sW;
    const unsigned long long* sb2 = (const unsigned long long*)sb;

    int n = n0 + threadIdx.x;
    if (n >= N_NODES) return;

    int b = __ldg(batch + n);

    const float* xr = sx + threadIdx.x * HID;
    unsigned long long acc[H2P];
#pragma unroll
    for (int p = 0; p < H2P; p++) acc[p] = sb2[p];
#pragma unroll
    for (int k = 0; k < HID; k++) {
        unsigned long long xk = bcast2(xr[k]);
#pragma unroll
        for (int p = 0; p < H2P; p++) acc[p] = fma2(xk, w2[k * H2P + p], acc[p]);
    }

    float y[H2];
#pragma unroll
    for (int p = 0; p < H2P; p++) {
        float2 t = unpack2(acc[p]);
        y[2*p]   = fmaxf(t.x, 0.f);
        y[2*p+1] = fmaxf(t.y, 0.f);
    }

    float* gr = g_g + (size_t)b * H2;
#pragma unroll
    for (int q = 0; q < 5; q++) {
        asm volatile("red.global.add.v2.f32 [%0], {%1,%2};"
                     :: "l"(gr + 2*q), "f"(y[2*q]), "f"(y[2*q+1])
                     : "memory");
    }
}

// ---------------------------------------------------------------------------
// Kernel 4: graph MLP
// ---------------------------------------------------------------------------
__global__ __launch_bounds__(256) void graph_mlp_kernel(
        const float* __restrict__ W2,
        const float* __restrict__ b2,
        const float* __restrict__ W3,
        const float* __restrict__ b3,
        float* __restrict__ out) {
    __shared__ float sW2[H2 * H2];
    __shared__ float sb2[H2];
    __shared__ float sW3[H2];
    __shared__ float sb3;
    for (int i = threadIdx.x; i < H2 * H2; i += blockDim.x) sW2[i] = W2[i];
    if (threadIdx.x < H2) { sb2[threadIdx.x] = b2[threadIdx.x]; sW3[threadIdx.x] = W3[threadIdx.x]; }
    if (threadIdx.x == 0) sb3 = b3[0];
    __syncthreads();

    int g = blockIdx.x * blockDim.x + threadIdx.x;
    if (g >= N_GRAPHS) return;

    float v[H2];
    const float2* gp = (const float2*)(g_g + (size_t)g * H2);
#pragma unroll
    for (int q = 0; q < 5; q++) {
        float2 t = gp[q];
        v[2*q] = t.x; v[2*q+1] = t.y;
    }

    float o = sb3;
#pragma unroll
    for (int j = 0; j < H2; j++) {
        float h = sb2[j];
#pragma unroll
        for (int k = 0; k < H2; k++) h = fmaf(v[k], sW2[k * H2 + j], h);
        o = fmaf(fmaxf(h, 0.f), sW3[j], o);
    }
    out[g] = o;
}

// ---------------------------------------------------------------------------
extern "C" void kernel_launch(void* const* d_in, const int* in_sizes, int n_in,
                              void* d_out, int out_size) {
    const int*   edge_index = (const int*)  d_in[0];
    const float* node_attr  = (const float*)d_in[1];
    const float* edge_attr  = (const float*)d_in[2];
    const int*   batch      = (const int*)  d_in[3];
    const float* W_msg      = (const float*)d_in[4];
    const float* b_msg      = (const float*)d_in[5];
    const float* W1         = (const float*)d_in[6];
    const float* b1         = (const float*)d_in[7];
    const float* W2         = (const float*)d_in[8];
    const float* b2         = (const float*)d_in[9];
    const float* W3         = (const float*)d_in[10];
    const float* b3         = (const float*)d_in[11];
    float* out = (float*)d_out;

    node_proj_kernel<<<2 * NPB, 256>>>(node_attr, W_msg);
    edge_kernel<<<(N_EDGES + 255) / 256, 256>>>(edge_index, edge_attr, W_msg, b_msg);
    node_mlp_kernel<<<NPB, 256>>>(batch, W1, b1);
    graph_mlp_kernel<<<(N_GRAPHS + 255) / 256, 256>>>(W2, b2, W3, b3, out);
}

// round 11
// speedup vs baseline: 1.6367x; 1.0152x over previous
#include <cuda_runtime.h>
#include <cuda_fp16.h>

#define N_NODES   100000
#define N_EDGES   1600000
#define N_GRAPHS  5000
#define ND        16
#define ED        16
#define HID       20
#define H2        10
#define HP        (HID/2)
#define H2P       (H2/2)
#define PH_STRIDE 32        // half stride per pa/pb row: 32 halves = 64B

// Scratch
__device__ float g_x [N_NODES * HID];
__device__ __align__(128) __half g_pa[N_NODES * PH_STRIDE];
__device__ __align__(128) __half g_pb[N_NODES * PH_STRIDE];
__device__ float g_g [N_GRAPHS * H2];

// ---- packed f32x2 helpers -------------------------------------------------
__device__ __forceinline__ unsigned long long fma2(unsigned long long a,
                                                   unsigned long long b,
                                                   unsigned long long c) {
    unsigned long long d;
    asm("fma.rn.f32x2 %0, %1, %2, %3;" : "=l"(d) : "l"(a), "l"(b), "l"(c));
    return d;
}
__device__ __forceinline__ unsigned long long bcast2(float x) {
    unsigned long long d;
    asm("mov.b64 %0, {%1, %1};" : "=l"(d) : "f"(x));
    return d;
}
__device__ __forceinline__ float2 unpack2(unsigned long long v) {
    float2 r;
    asm("mov.b64 {%0, %1}, %2;" : "=f"(r.x), "=f"(r.y) : "l"(v));
    return r;
}
__device__ __forceinline__ float2 h2f2(unsigned int h) {
    return __half22float2(*(const __half2*)&h);
}

// 256-bit load (Blackwell)
__device__ __forceinline__ void ldg256(const void* p, float r[8]) {
    asm("ld.global.nc.v8.f32 {%0,%1,%2,%3,%4,%5,%6,%7}, [%8];"
        : "=f"(r[0]), "=f"(r[1]), "=f"(r[2]), "=f"(r[3]),
          "=f"(r[4]), "=f"(r[5]), "=f"(r[6]), "=f"(r[7])
        : "l"(p));
}
__device__ __forceinline__ float2 ldg64(const void* p) {
    float2 r;
    asm("ld.global.nc.v2.f32 {%0,%1}, [%2];" : "=f"(r.x), "=f"(r.y) : "l"(p));
    return r;
}

// ---------------------------------------------------------------------------
// Kernel 1: per-node projections, fully coalesced global traffic.
// All strided accesses (node_attr in, pa/pb out, g_x zero) go through smem
// staging with linear coalesced global ops.
// ---------------------------------------------------------------------------
__global__ __launch_bounds__(256) void node_proj_kernel(
        const float* __restrict__ node_attr,
        const float* __restrict__ W_msg) {
    __shared__ __align__(8)  float sWa[ND * HID];
    __shared__ __align__(8)  float sWb[ND * HID];
    __shared__ __align__(16) float sattr[256 * ND];     // 16 KB
    __shared__ unsigned int sout[256 * 17];             // 17 KB, bank-safe stride

    const int tid = threadIdx.x;
    for (int i = tid; i < ND * HID; i += 256) {
        sWa[i] = W_msg[i];
        sWb[i] = W_msg[ND * HID + i];
    }

    const int n0 = blockIdx.x * 256;
    int rows = N_NODES - n0; if (rows > 256) rows = 256;

    // coalesced zero of g_x rows [n0, n0+rows)
    {
        const float4 z = make_float4(0.f, 0.f, 0.f, 0.f);
        float4* xz = (float4*)(g_x + (size_t)n0 * HID);
        const int nf4 = rows * (HID / 4);
        for (int i = tid; i < nf4; i += 256) xz[i] = z;
    }
    // g_g zero, spread over grid
    {
        int gi = n0 + tid;
        if (gi < (N_GRAPHS * H2) / 4)
            ((float4*)g_g)[gi] = make_float4(0.f, 0.f, 0.f, 0.f);
    }
    // stage node_attr (contiguous 16KB) coalesced
    {
        const float4* src = (const float4*)(node_attr + (size_t)n0 * ND);
        const int nf4 = rows * (ND / 4);
        for (int i = tid; i < nf4; i += 256) ((float4*)sattr)[i] = src[i];
    }
    __syncthreads();

    const unsigned long long* wa2 = (const unsigned long long*)sWa;
    const unsigned long long* wb2 = (const unsigned long long*)sWb;
    const bool active = (tid < rows);

    float a[ND];
    if (active) {
        const float* ar = sattr + tid * ND;
#pragma unroll
        for (int k = 0; k < ND; k++) a[k] = ar[k];
    }

    // ---- pa: compute, pack fp16, stage ----
    if (active) {
        unsigned long long acc[HP];
#pragma unroll
        for (int p = 0; p < HP; p++) acc[p] = 0ull;
#pragma unroll
        for (int k = 0; k < ND; k++) {
            unsigned long long ak = bcast2(a[k]);
#pragma unroll
            for (int p = 0; p < HP; p++) acc[p] = fma2(ak, wa2[k * HP + p], acc[p]);
        }
#pragma unroll
        for (int p = 0; p < HP; p++) {
            float2 t = unpack2(acc[p]);
            __half2 h = __float22half2_rn(t);
            sout[tid * 17 + p] = *(unsigned int*)&h;
        }
    }
    __syncthreads();
    // coalesced writeback of padded 64B rows (pad bytes = junk, never read)
    {
        unsigned int* dst = (unsigned int*)((char*)g_pa + (size_t)n0 * 64);
        const int nu = rows * 16;
        for (int i = tid; i < nu; i += 256)
            dst[i] = sout[(i >> 4) * 17 + (i & 15)];
    }
    __syncthreads();

    // ---- pb ----
    if (active) {
        unsigned long long acc[HP];
#pragma unroll
        for (int p = 0; p < HP; p++) acc[p] = 0ull;
#pragma unroll
        for (int k = 0; k < ND; k++) {
            unsigned long long ak = bcast2(a[k]);
#pragma unroll
            for (int p = 0; p < HP; p++) acc[p] = fma2(ak, wb2[k * HP + p], acc[p]);
        }
#pragma unroll
        for (int p = 0; p < HP; p++) {
            float2 t = unpack2(acc[p]);
            __half2 h = __float22half2_rn(t);
            sout[tid * 17 + p] = *(unsigned int*)&h;
        }
    }
    __syncthreads();
    {
        unsigned int* dst = (unsigned int*)((char*)g_pb + (size_t)n0 * 64);
        const int nu = rows * 16;
        for (int i = tid; i < nu; i += 256)
            dst[i] = sout[(i >> 4) * 17 + (i & 15)];
    }
}

// ---------------------------------------------------------------------------
// Kernel 2: edge message + scatter-sum (exact R6 hot path)
// ---------------------------------------------------------------------------
__global__ __launch_bounds__(256) void edge_kernel(
        const int*   __restrict__ edge_index,
        const float* __restrict__ edge_attr,
        const float* __restrict__ W_msg,
        const float* __restrict__ b_msg) {
    __shared__ __align__(8) float sWe[ED * HID];
    __shared__ __align__(8) float sb[HID];
    for (int i = threadIdx.x; i < ED * HID; i += blockDim.x)
        sWe[i] = W_msg[2 * ND * HID + i];
    for (int i = threadIdx.x; i < HID; i += blockDim.x)
        sb[i] = b_msg[i];
    __syncthreads();
    const unsigned long long* we2 = (const unsigned long long*)sWe;
    const unsigned long long* sb2 = (const unsigned long long*)sb;

    int e = blockIdx.x * blockDim.x + threadIdx.x;
    if (e >= N_EDGES) return;

    int src = __ldg(edge_index + e);
    int dst = __ldg(edge_index + N_EDGES + e);

    const char* par = (const char*)(g_pa + (size_t)src * PH_STRIDE);
    const char* pbr = (const char*)(g_pb + (size_t)dst * PH_STRIDE);
    float A8[8], B8[8];
    ldg256(par, A8);
    float2 A2 = ldg64(par + 32);
    ldg256(pbr, B8);
    float2 B2 = ldg64(pbr + 32);

    float ea[ED];
    ldg256(edge_attr + (size_t)e * ED, ea);
    ldg256(edge_attr + (size_t)e * ED + 8, ea + 8);

    unsigned long long acc[HP];
#pragma unroll
    for (int p = 0; p < HP; p++) acc[p] = sb2[p];

#pragma unroll
    for (int k = 0; k < ED; k++) {
        unsigned long long b = bcast2(ea[k]);
#pragma unroll
        for (int p = 0; p < HP; p++)
            acc[p] = fma2(b, we2[k * HP + p], acc[p]);
    }

    unsigned int au[HP] = {
        __float_as_uint(A8[0]), __float_as_uint(A8[1]), __float_as_uint(A8[2]),
        __float_as_uint(A8[3]), __float_as_uint(A8[4]), __float_as_uint(A8[5]),
        __float_as_uint(A8[6]), __float_as_uint(A8[7]),
        __float_as_uint(A2.x),  __float_as_uint(A2.y)};
    unsigned int bu[HP] = {
        __float_as_uint(B8[0]), __float_as_uint(B8[1]), __float_as_uint(B8[2]),
        __float_as_uint(B8[3]), __float_as_uint(B8[4]), __float_as_uint(B8[5]),
        __float_as_uint(B8[6]), __float_as_uint(B8[7]),
        __float_as_uint(B2.x),  __float_as_uint(B2.y)};

    float m[HID];
#pragma unroll
    for (int p = 0; p < HP; p++) {
        float2 c = unpack2(acc[p]);
        float2 fa = h2f2(au[p]);
        float2 fb = h2f2(bu[p]);
        m[2*p]   = fmaxf(c.x + fa.x + fb.x, 0.f);
        m[2*p+1] = fmaxf(c.y + fa.y + fb.y, 0.f);
    }

    float* xr = g_x + (size_t)dst * HID;
#pragma unroll
    for (int q = 0; q < 5; q++) {
        asm volatile("red.global.add.v4.f32 [%0], {%1,%2,%3,%4};"
                     :: "l"(xr + 4*q),
                        "f"(m[4*q]), "f"(m[4*q+1]), "f"(m[4*q+2]), "f"(m[4*q+3])
                     : "memory");
    }
}

// ---------------------------------------------------------------------------
// Kernel 3: node MLP + graph pooling (exact R6)
// ---------------------------------------------------------------------------
__global__ __launch_bounds__(128) void node_mlp_kernel(
        const int*   __restrict__ batch,
        const float* __restrict__ W1,
        const float* __restrict__ b1) {
    __shared__ __align__(8) float sW[HID * H2];
    __shared__ __align__(8) float sb[H2];
    for (int i = threadIdx.x; i < HID * H2; i += blockDim.x) sW[i] = W1[i];
    for (int i = threadIdx.x; i < H2; i += blockDim.x) sb[i] = b1[i];
    __syncthreads();
    const unsigned long long* w2 = (const unsigned long long*)sW;
    const unsigned long long* sb2 = (const unsigned long long*)sb;

    int n = blockIdx.x * blockDim.x + threadIdx.x;
    if (n >= N_NODES) return;

    int b = __ldg(batch + n);

    float x[HID];
    const float4* xp = (const float4*)(g_x + (size_t)n * HID);
#pragma unroll
    for (int q = 0; q < 5; q++) {
        float4 v = xp[q];
        x[4*q+0] = v.x; x[4*q+1] = v.y; x[4*q+2] = v.z; x[4*q+3] = v.w;
    }

    unsigned long long acc[H2P];
#pragma unroll
    for (int p = 0; p < H2P; p++) acc[p] = sb2[p];
#pragma unroll
    for (int k = 0; k < HID; k++) {
        unsigned long long xk = bcast2(x[k]);
#pragma unroll
        for (int p = 0; p < H2P; p++) acc[p] = fma2(xk, w2[k * H2P + p], acc[p]);
    }

    float y[H2];
#pragma unroll
    for (int p = 0; p < H2P; p++) {
        float2 t = unpack2(acc[p]);
        y[2*p]   = fmaxf(t.x, 0.f);
        y[2*p+1] = fmaxf(t.y, 0.f);
    }

    float* gr = g_g + (size_t)b * H2;
#pragma unroll
    for (int q = 0; q < 5; q++) {
        asm volatile("red.global.add.v2.f32 [%0], {%1,%2};"
                     :: "l"(gr + 2*q), "f"(y[2*q]), "f"(y[2*q+1])
                     : "memory");
    }
}

// ---------------------------------------------------------------------------
// Kernel 4: graph MLP (exact R6)
// ---------------------------------------------------------------------------
__global__ __launch_bounds__(256) void graph_mlp_kernel(
        const float* __restrict__ W2,
        const float* __restrict__ b2,
        const float* __restrict__ W3,
        const float* __restrict__ b3,
        float* __restrict__ out) {
    __shared__ float sW2[H2 * H2];
    __shared__ float sb2[H2];
    __shared__ float sW3[H2];
    __shared__ float sb3;
    for (int i = threadIdx.x; i < H2 * H2; i += blockDim.x) sW2[i] = W2[i];
    if (threadIdx.x < H2) { sb2[threadIdx.x] = b2[threadIdx.x]; sW3[threadIdx.x] = W3[threadIdx.x]; }
    if (threadIdx.x == 0) sb3 = b3[0];
    __syncthreads();

    int g = blockIdx.x * blockDim.x + threadIdx.x;
    if (g >= N_GRAPHS) return;

    float v[H2];
    const float2* gp = (const float2*)(g_g + (size_t)g * H2);
#pragma unroll
    for (int q = 0; q < 5; q++) {
        float2 t = gp[q];
        v[2*q] = t.x; v[2*q+1] = t.y;
    }

    float o = sb3;
#pragma unroll
    for (int j = 0; j < H2; j++) {
        float h = sb2[j];
#pragma unroll
        for (int k = 0; k < H2; k++) h = fmaf(v[k], sW2[k * H2 + j], h);
        o = fmaf(fmaxf(h, 0.f), sW3[j], o);
    }
    out[g] = o;
}

// ---------------------------------------------------------------------------
extern "C" void kernel_launch(void* const* d_in, const int* in_sizes, int n_in,
                              void* d_out, int out_size) {
    const int*   edge_index = (const int*)  d_in[0];
    const float* node_attr  = (const float*)d_in[1];
    const float* edge_attr  = (const float*)d_in[2];
    const int*   batch      = (const int*)  d_in[3];
    const float* W_msg      = (const float*)d_in[4];
    const float* b_msg      = (const float*)d_in[5];
    const float* W1         = (const float*)d_in[6];
    const float* b1         = (const float*)d_in[7];
    const float* W2         = (const float*)d_in[8];
    const float* b2         = (const float*)d_in[9];
    const float* W3         = (const float*)d_in[10];
    const float* b3         = (const float*)d_in[11];
    float* out = (float*)d_out;

    node_proj_kernel<<<(N_NODES + 255) / 256, 256>>>(node_attr, W_msg);
    edge_kernel<<<(N_EDGES + 255) / 256, 256>>>(edge_index, edge_attr, W_msg, b_msg);
    node_mlp_kernel<<<(N_NODES + 127) / 128, 128>>>(batch, W1, b1);
    graph_mlp_kernel<<<(N_GRAPHS + 255) / 256, 256>>>(W2, b2, W3, b3, out);
}

// round 13
// speedup vs baseline: 1.8128x; 1.1075x over previous
#include <cuda_runtime.h>
#include <cuda_fp16.h>

#define N_NODES   100000
#define N_EDGES   1600000
#define N_GRAPHS  5000
#define ND        16
#define ED        16
#define HID       20
#define H2        10
#define HP        (HID/2)
#define H2P       (H2/2)
#define PH_STRIDE 32        // half stride per pa/pb row: 64B
#define XH_STRIDE 32        // half stride per g_x row: 64B (32B-aligned v8 loads)

// Scratch
__device__ __align__(128) __half g_x [N_NODES * XH_STRIDE];  // fp16 accumulators
__device__ __align__(128) __half g_pa[N_NODES * PH_STRIDE];
__device__ __align__(128) __half g_pb[N_NODES * PH_STRIDE];
__device__ float g_g [N_GRAPHS * H2];

// ---- packed f32x2 helpers -------------------------------------------------
__device__ __forceinline__ unsigned long long fma2(unsigned long long a,
                                                   unsigned long long b,
                                                   unsigned long long c) {
    unsigned long long d;
    asm("fma.rn.f32x2 %0, %1, %2, %3;" : "=l"(d) : "l"(a), "l"(b), "l"(c));
    return d;
}
__device__ __forceinline__ unsigned long long bcast2(float x) {
    unsigned long long d;
    asm("mov.b64 %0, {%1, %1};" : "=l"(d) : "f"(x));
    return d;
}
__device__ __forceinline__ float2 unpack2(unsigned long long v) {
    float2 r;
    asm("mov.b64 {%0, %1}, %2;" : "=f"(r.x), "=f"(r.y) : "l"(v));
    return r;
}
__device__ __forceinline__ float2 h2f2(unsigned int h) {
    return __half22float2(*(const __half2*)&h);
}

// 256-bit load (Blackwell) — requires 32B-aligned address
__device__ __forceinline__ void ldg256(const void* p, float r[8]) {
    asm("ld.global.nc.v8.f32 {%0,%1,%2,%3,%4,%5,%6,%7}, [%8];"
        : "=f"(r[0]), "=f"(r[1]), "=f"(r[2]), "=f"(r[3]),
          "=f"(r[4]), "=f"(r[5]), "=f"(r[6]), "=f"(r[7])
        : "l"(p));
}
__device__ __forceinline__ float2 ldg64(const void* p) {
    float2 r;
    asm("ld.global.nc.v2.f32 {%0,%1}, [%2];" : "=f"(r.x), "=f"(r.y) : "l"(p));
    return r;
}

// ---------------------------------------------------------------------------
// Kernel 1: per-node projections pa = A@Wa, pb = A@Wb  (fp16 out, + zeroing)
// ---------------------------------------------------------------------------
__global__ void node_proj_kernel(const float* __restrict__ node_attr,
                                 const float* __restrict__ W_msg) {
    __shared__ __align__(8) float sWa[ND * HID];
    __shared__ __align__(8) float sWb[ND * HID];
    for (int i = threadIdx.x; i < ND * HID; i += blockDim.x) {
        sWa[i] = W_msg[i];
        sWb[i] = W_msg[ND * HID + i];
    }
    __syncthreads();
    const unsigned long long* wa2 = (const unsigned long long*)sWa;
    const unsigned long long* wb2 = (const unsigned long long*)sWb;

    int n = blockIdx.x * blockDim.x + threadIdx.x;

    if (n < (N_GRAPHS * H2) / 4)
        ((float4*)g_g)[n] = make_float4(0.f, 0.f, 0.f, 0.f);

    if (n >= N_NODES) return;

    // zero this node's fp16 g_x row (only the 40B used, in aligned 16B chunks + 8B)
    {
        char* xr = (char*)g_x + (size_t)n * 64;
        const uint4 z4 = make_uint4(0u, 0u, 0u, 0u);
        *(uint4*)(xr)      = z4;
        *(uint4*)(xr + 16) = z4;
        *(uint2*)(xr + 32) = make_uint2(0u, 0u);
    }

    float a[ND];
    const float4* ap = (const float4*)(node_attr + (size_t)n * ND);
#pragma unroll
    for (int q = 0; q < 4; q++) {
        float4 v = ap[q];
        a[4*q+0] = v.x; a[4*q+1] = v.y; a[4*q+2] = v.z; a[4*q+3] = v.w;
    }

    unsigned long long acc[HP];
    unsigned int u[HP];

    // pa
#pragma unroll
    for (int p = 0; p < HP; p++) acc[p] = 0ull;
#pragma unroll
    for (int k = 0; k < ND; k++) {
        unsigned long long ak = bcast2(a[k]);
#pragma unroll
        for (int p = 0; p < HP; p++) acc[p] = fma2(ak, wa2[k * HP + p], acc[p]);
    }
#pragma unroll
    for (int p = 0; p < HP; p++) {
        float2 t = unpack2(acc[p]);
        __half2 h = __float22half2_rn(t);
        u[p] = *(unsigned int*)&h;
    }
    {
        char* row = (char*)(g_pa + (size_t)n * PH_STRIDE);
        *(uint4*)(row +  0) = make_uint4(u[0], u[1], u[2], u[3]);
        *(uint4*)(row + 16) = make_uint4(u[4], u[5], u[6], u[7]);
        *(uint2*)(row + 32) = make_uint2(u[8], u[9]);
    }

    // pb
#pragma unroll
    for (int p = 0; p < HP; p++) acc[p] = 0ull;
#pragma unroll
    for (int k = 0; k < ND; k++) {
        unsigned long long ak = bcast2(a[k]);
#pragma unroll
        for (int p = 0; p < HP; p++) acc[p] = fma2(ak, wb2[k * HP + p], acc[p]);
    }
#pragma unroll
    for (int p = 0; p < HP; p++) {
        float2 t = unpack2(acc[p]);
        __half2 h = __float22half2_rn(t);
        u[p] = *(unsigned int*)&h;
    }
    {
        char* row = (char*)(g_pb + (size_t)n * PH_STRIDE);
        *(uint4*)(row +  0) = make_uint4(u[0], u[1], u[2], u[3]);
        *(uint4*)(row + 16) = make_uint4(u[4], u[5], u[6], u[7]);
        *(uint2*)(row + 32) = make_uint2(u[8], u[9]);
    }
}

// ---------------------------------------------------------------------------
// Kernel 2: edge message + scatter-sum (v8 loads; fp16x2 vector reductions)
// ---------------------------------------------------------------------------
__global__ __launch_bounds__(256) void edge_kernel(
        const int*   __restrict__ edge_index,
        const float* __restrict__ edge_attr,
        const float* __restrict__ W_msg,
        const float* __restrict__ b_msg) {
    __shared__ __align__(8) float sWe[ED * HID];
    __shared__ __align__(8) float sb[HID];
    for (int i = threadIdx.x; i < ED * HID; i += blockDim.x)
        sWe[i] = W_msg[2 * ND * HID + i];
    for (int i = threadIdx.x; i < HID; i += blockDim.x)
        sb[i] = b_msg[i];
    __syncthreads();
    const unsigned long long* we2 = (const unsigned long long*)sWe;
    const unsigned long long* sb2 = (const unsigned long long*)sb;

    int e = blockIdx.x * blockDim.x + threadIdx.x;
    if (e >= N_EDGES) return;

    int src = __ldg(edge_index + e);
    int dst = __ldg(edge_index + N_EDGES + e);

    const char* par = (const char*)(g_pa + (size_t)src * PH_STRIDE);
    const char* pbr = (const char*)(g_pb + (size_t)dst * PH_STRIDE);
    float A8[8], B8[8];
    ldg256(par, A8);
    float2 A2 = ldg64(par + 32);
    ldg256(pbr, B8);
    float2 B2 = ldg64(pbr + 32);

    float ea[ED];
    ldg256(edge_attr + (size_t)e * ED, ea);
    ldg256(edge_attr + (size_t)e * ED + 8, ea + 8);

    unsigned long long acc[HP];
#pragma unroll
    for (int p = 0; p < HP; p++) acc[p] = sb2[p];

#pragma unroll
    for (int k = 0; k < ED; k++) {
        unsigned long long b = bcast2(ea[k]);
#pragma unroll
        for (int p = 0; p < HP; p++)
            acc[p] = fma2(b, we2[k * HP + p], acc[p]);
    }

    unsigned int au[HP] = {
        __float_as_uint(A8[0]), __float_as_uint(A8[1]), __float_as_uint(A8[2]),
        __float_as_uint(A8[3]), __float_as_uint(A8[4]), __float_as_uint(A8[5]),
        __float_as_uint(A8[6]), __float_as_uint(A8[7]),
        __float_as_uint(A2.x),  __float_as_uint(A2.y)};
    unsigned int bu[HP] = {
        __float_as_uint(B8[0]), __float_as_uint(B8[1]), __float_as_uint(B8[2]),
        __float_as_uint(B8[3]), __float_as_uint(B8[4]), __float_as_uint(B8[5]),
        __float_as_uint(B8[6]), __float_as_uint(B8[7]),
        __float_as_uint(B2.x),  __float_as_uint(B2.y)};

    // message packed to fp16x2 pairs
    unsigned int mh[HP];
#pragma unroll
    for (int p = 0; p < HP; p++) {
        float2 c = unpack2(acc[p]);
        float2 fa = h2f2(au[p]);
        float2 fb = h2f2(bu[p]);
        float2 mm;
        mm.x = fmaxf(c.x + fa.x + fb.x, 0.f);
        mm.y = fmaxf(c.y + fa.y + fb.y, 0.f);
        __half2 h = __float22half2_rn(mm);
        mh[p] = *(unsigned int*)&h;
    }

    char* xr = (char*)g_x + (size_t)dst * 64;   // 64B rows
    asm volatile("red.global.add.noftz.v4.f16x2 [%0], {%1,%2,%3,%4};"
                 :: "l"(xr), "r"(mh[0]), "r"(mh[1]), "r"(mh[2]), "r"(mh[3]) : "memory");
    asm volatile("red.global.add.noftz.v4.f16x2 [%0], {%1,%2,%3,%4};"
                 :: "l"(xr + 16), "r"(mh[4]), "r"(mh[5]), "r"(mh[6]), "r"(mh[7]) : "memory");
    asm volatile("red.global.add.noftz.v2.f16x2 [%0], {%1,%2};"
                 :: "l"(xr + 32), "r"(mh[8]), "r"(mh[9]) : "memory");
}

// ---------------------------------------------------------------------------
// Kernel 3: node MLP + graph pooling (fp16 g_x reads, 32B-aligned rows)
// ---------------------------------------------------------------------------
__global__ __launch_bounds__(128) void node_mlp_kernel(
        const int*   __restrict__ batch,
        const float* __restrict__ W1,
        const float* __restrict__ b1) {
    __shared__ __align__(8) float sW[HID * H2];
    __shared__ __align__(8) float sb[H2];
    for (int i = threadIdx.x; i < HID * H2; i += blockDim.x) sW[i] = W1[i];
    for (int i = threadIdx.x; i < H2; i += blockDim.x) sb[i] = b1[i];
    __syncthreads();
    const unsigned long long* w2 = (const unsigned long long*)sW;
    const unsigned long long* sb2 = (const unsigned long long*)sb;

    int n = blockIdx.x * blockDim.x + threadIdx.x;
    if (n >= N_NODES) return;

    int b = __ldg(batch + n);

    // 64B row: v8 (32B = 16 halves, 64B-aligned base) + v2 (8B = 4 halves)
    const char* xrow = (const char*)g_x + (size_t)n * 64;
    float X8[8];
    ldg256(xrow, X8);
    float2 X2 = ldg64(xrow + 32);
    unsigned int xu[HP] = {
        __float_as_uint(X8[0]), __float_as_uint(X8[1]), __float_as_uint(X8[2]),
        __float_as_uint(X8[3]), __float_as_uint(X8[4]), __float_as_uint(X8[5]),
        __float_as_uint(X8[6]), __float_as_uint(X8[7]),
        __float_as_uint(X2.x),  __float_as_uint(X2.y)};

    float x[HID];
#pragma unroll
    for (int p = 0; p < HP; p++) {
        float2 t = h2f2(xu[p]);
        x[2*p] = t.x; x[2*p+1] = t.y;
    }

    unsigned long long acc[H2P];
#pragma unroll
    for (int p = 0; p < H2P; p++) acc[p] = sb2[p];
#pragma unroll
    for (int k = 0; k < HID; k++) {
        unsigned long long xk = bcast2(x[k]);
#pragma unroll
        for (int p = 0; p < H2P; p++) acc[p] = fma2(xk, w2[k * H2P + p], acc[p]);
    }

    float y[H2];
#pragma unroll
    for (int p = 0; p < H2P; p++) {
        float2 t = unpack2(acc[p]);
        y[2*p]   = fmaxf(t.x, 0.f);
        y[2*p+1] = fmaxf(t.y, 0.f);
    }

    float* gr = g_g + (size_t)b * H2;
#pragma unroll
    for (int q = 0; q < 5; q++) {
        asm volatile("red.global.add.v2.f32 [%0], {%1,%2};"
                     :: "l"(gr + 2*q), "f"(y[2*q]), "f"(y[2*q+1])
                     : "memory");
    }
}

// ---------------------------------------------------------------------------
// Kernel 4: graph MLP
// ---------------------------------------------------------------------------
__global__ __launch_bounds__(256) void graph_mlp_kernel(
        const float* __restrict__ W2,
        const float* __restrict__ b2,
        const float* __restrict__ W3,
        const float* __restrict__ b3,
        float* __restrict__ out) {
    __shared__ float sW2[H2 * H2];
    __shared__ float sb2[H2];
    __shared__ float sW3[H2];
    __shared__ float sb3;
    for (int i = threadIdx.x; i < H2 * H2; i += blockDim.x) sW2[i] = W2[i];
    if (threadIdx.x < H2) { sb2[threadIdx.x] = b2[threadIdx.x]; sW3[threadIdx.x] = W3[threadIdx.x]; }
    if (threadIdx.x == 0) sb3 = b3[0];
    __syncthreads();

    int g = blockIdx.x * blockDim.x + threadIdx.x;
    if (g >= N_GRAPHS) return;

    float v[H2];
    const float2* gp = (const float2*)(g_g + (size_t)g * H2);
#pragma unroll
    for (int q = 0; q < 5; q++) {
        float2 t = gp[q];
        v[2*q] = t.x; v[2*q+1] = t.y;
    }

    float o = sb3;
#pragma unroll
    for (int j = 0; j < H2; j++) {
        float h = sb2[j];
#pragma unroll
        for (int k = 0; k < H2; k++) h = fmaf(v[k], sW2[k * H2 + j], h);
        o = fmaf(fmaxf(h, 0.f), sW3[j], o);
    }
    out[g] = o;
}

// ---------------------------------------------------------------------------
extern "C" void kernel_launch(void* const* d_in, const int* in_sizes, int n_in,
                              void* d_out, int out_size) {
    const int*   edge_index = (const int*)  d_in[0];
    const float* node_attr  = (const float*)d_in[1];
    const float* edge_attr  = (const float*)d_in[2];
    const int*   batch      = (const int*)  d_in[3];
    const float* W_msg      = (const float*)d_in[4];
    const float* b_msg      = (const float*)d_in[5];
    const float* W1         = (const float*)d_in[6];
    const float* b1         = (const float*)d_in[7];
    const float* W2         = (const float*)d_in[8];
    const float* b2         = (const float*)d_in[9];
    const float* W3         = (const float*)d_in[10];
    const float* b3         = (const float*)d_in[11];
    float* out = (float*)d_out;

    node_proj_kernel<<<(N_NODES + 255) / 256, 256>>>(node_attr, W_msg);
    edge_kernel<<<(N_EDGES + 255) / 256, 256>>>(edge_index, edge_attr, W_msg, b_msg);
    node_mlp_kernel<<<(N_NODES + 127) / 128, 128>>>(batch, W1, b1);
    graph_mlp_kernel<<<(N_GRAPHS + 255) / 256, 256>>>(W2, b2, W3, b3, out);
}

// round 14
// speedup vs baseline: 1.8554x; 1.0235x over previous
#include <cuda_runtime.h>
#include <cuda_fp16.h>

#define N_NODES   100000
#define N_EDGES   1600000
#define N_GRAPHS  5000
#define ND        16
#define ED        16
#define HID       20
#define H2        10
#define HP        (HID/2)
#define H2P       (H2/2)
#define PH_STRIDE 32        // half stride per pa/pb row: 64B
#define XH_STRIDE 32        // half stride per g_x row: 64B

// Scratch
__device__ __align__(128) __half g_x [N_NODES * XH_STRIDE];  // fp16 accumulators
__device__ __align__(128) __half g_pa[N_NODES * PH_STRIDE];
__device__ __align__(128) __half g_pb[N_NODES * PH_STRIDE];
__device__ float g_g [N_GRAPHS * H2];

// ---- packed f32x2 helpers -------------------------------------------------
__device__ __forceinline__ unsigned long long fma2(unsigned long long a,
                                                   unsigned long long b,
                                                   unsigned long long c) {
    unsigned long long d;
    asm("fma.rn.f32x2 %0, %1, %2, %3;" : "=l"(d) : "l"(a), "l"(b), "l"(c));
    return d;
}
__device__ __forceinline__ unsigned long long bcast2(float x) {
    unsigned long long d;
    asm("mov.b64 %0, {%1, %1};" : "=l"(d) : "f"(x));
    return d;
}
__device__ __forceinline__ float2 unpack2(unsigned long long v) {
    float2 r;
    asm("mov.b64 {%0, %1}, %2;" : "=f"(r.x), "=f"(r.y) : "l"(v));
    return r;
}
__device__ __forceinline__ float2 h2f2(unsigned int h) {
    return __half22float2(*(const __half2*)&h);
}

// 256-bit load (Blackwell) — requires 32B-aligned address
__device__ __forceinline__ void ldg256(const void* p, float r[8]) {
    asm("ld.global.nc.v8.f32 {%0,%1,%2,%3,%4,%5,%6,%7}, [%8];"
        : "=f"(r[0]), "=f"(r[1]), "=f"(r[2]), "=f"(r[3]),
          "=f"(r[4]), "=f"(r[5]), "=f"(r[6]), "=f"(r[7])
        : "l"(p));
}
__device__ __forceinline__ float2 ldg64(const void* p) {
    float2 r;
    asm("ld.global.nc.v2.f32 {%0,%1}, [%2];" : "=f"(r.x), "=f"(r.y) : "l"(p));
    return r;
}

// ---------------------------------------------------------------------------
// Kernel 1: per-node projections pa = A@Wa, pb = A@Wb  (fp16 out, + zeroing)
// 128-thread blocks for higher grid occupancy.
// ---------------------------------------------------------------------------
__global__ __launch_bounds__(128) void node_proj_kernel(
        const float* __restrict__ node_attr,
        const float* __restrict__ W_msg) {
    __shared__ __align__(8) float sWa[ND * HID];
    __shared__ __align__(8) float sWb[ND * HID];
    for (int i = threadIdx.x; i < ND * HID; i += blockDim.x) {
        sWa[i] = W_msg[i];
        sWb[i] = W_msg[ND * HID + i];
    }
    __syncthreads();
    const unsigned long long* wa2 = (const unsigned long long*)sWa;
    const unsigned long long* wb2 = (const unsigned long long*)sWb;

    int n = blockIdx.x * blockDim.x + threadIdx.x;

    if (n < (N_GRAPHS * H2) / 4)
        ((float4*)g_g)[n] = make_float4(0.f, 0.f, 0.f, 0.f);

    if (n >= N_NODES) return;

    // zero this node's fp16 g_x row
    {
        char* xr = (char*)g_x + (size_t)n * 64;
        const uint4 z4 = make_uint4(0u, 0u, 0u, 0u);
        *(uint4*)(xr)      = z4;
        *(uint4*)(xr + 16) = z4;
        *(uint2*)(xr + 32) = make_uint2(0u, 0u);
    }

    float a[ND];
    const float4* ap = (const float4*)(node_attr + (size_t)n * ND);
#pragma unroll
    for (int q = 0; q < 4; q++) {
        float4 v = ap[q];
        a[4*q+0] = v.x; a[4*q+1] = v.y; a[4*q+2] = v.z; a[4*q+3] = v.w;
    }

    unsigned long long acc[HP];
    unsigned int u[HP];

    // pa
#pragma unroll
    for (int p = 0; p < HP; p++) acc[p] = 0ull;
#pragma unroll
    for (int k = 0; k < ND; k++) {
        unsigned long long ak = bcast2(a[k]);
#pragma unroll
        for (int p = 0; p < HP; p++) acc[p] = fma2(ak, wa2[k * HP + p], acc[p]);
    }
#pragma unroll
    for (int p = 0; p < HP; p++) {
        float2 t = unpack2(acc[p]);
        __half2 h = __float22half2_rn(t);
        u[p] = *(unsigned int*)&h;
    }
    {
        char* row = (char*)(g_pa + (size_t)n * PH_STRIDE);
        *(uint4*)(row +  0) = make_uint4(u[0], u[1], u[2], u[3]);
        *(uint4*)(row + 16) = make_uint4(u[4], u[5], u[6], u[7]);
        *(uint2*)(row + 32) = make_uint2(u[8], u[9]);
    }

    // pb
#pragma unroll
    for (int p = 0; p < HP; p++) acc[p] = 0ull;
#pragma unroll
    for (int k = 0; k < ND; k++) {
        unsigned long long ak = bcast2(a[k]);
#pragma unroll
        for (int p = 0; p < HP; p++) acc[p] = fma2(ak, wb2[k * HP + p], acc[p]);
    }
#pragma unroll
    for (int p = 0; p < HP; p++) {
        float2 t = unpack2(acc[p]);
        __half2 h = __float22half2_rn(t);
        u[p] = *(unsigned int*)&h;
    }
    {
        char* row = (char*)(g_pb + (size_t)n * PH_STRIDE);
        *(uint4*)(row +  0) = make_uint4(u[0], u[1], u[2], u[3]);
        *(uint4*)(row + 16) = make_uint4(u[4], u[5], u[6], u[7]);
        *(uint2*)(row + 32) = make_uint2(u[8], u[9]);
    }
}

// ---------------------------------------------------------------------------
// Kernel 2: edge message + scatter-sum (PDL consumer of node_proj)
// ---------------------------------------------------------------------------
__global__ __launch_bounds__(256) void edge_kernel(
        const int*   __restrict__ edge_index,
        const float* __restrict__ edge_attr,
        const float* __restrict__ W_msg,
        const float* __restrict__ b_msg) {
    __shared__ __align__(8) float sWe[ED * HID];
    __shared__ __align__(8) float sb[HID];
    for (int i = threadIdx.x; i < ED * HID; i += blockDim.x)
        sWe[i] = W_msg[2 * ND * HID + i];
    for (int i = threadIdx.x; i < HID; i += blockDim.x)
        sb[i] = b_msg[i];
    __syncthreads();
    const unsigned long long* we2 = (const unsigned long long*)sWe;
    const unsigned long long* sb2 = (const unsigned long long*)sb;

    int e = blockIdx.x * blockDim.x + threadIdx.x;
    if (e >= N_EDGES) {
        cudaGridDependencySynchronize();
        return;
    }

    // inputs not produced by node_proj: load before the dependency sync
    int src = __ldg(edge_index + e);
    int dst = __ldg(edge_index + N_EDGES + e);
    float ea[ED];
    ldg256(edge_attr + (size_t)e * ED, ea);
    ldg256(edge_attr + (size_t)e * ED + 8, ea + 8);

    // start the We matmul too (only needs inputs)
    unsigned long long acc[HP];
#pragma unroll
    for (int p = 0; p < HP; p++) acc[p] = sb2[p];
#pragma unroll
    for (int k = 0; k < ED; k++) {
        unsigned long long b = bcast2(ea[k]);
#pragma unroll
        for (int p = 0; p < HP; p++)
            acc[p] = fma2(b, we2[k * HP + p], acc[p]);
    }

    // wait for node_proj's g_pa/g_pb (and g_x zeroing)
    cudaGridDependencySynchronize();

    const char* par = (const char*)(g_pa + (size_t)src * PH_STRIDE);
    const char* pbr = (const char*)(g_pb + (size_t)dst * PH_STRIDE);
    float A8[8], B8[8];
    ldg256(par, A8);
    float2 A2 = ldg64(par + 32);
    ldg256(pbr, B8);
    float2 B2 = ldg64(pbr + 32);

    unsigned int au[HP] = {
        __float_as_uint(A8[0]), __float_as_uint(A8[1]), __float_as_uint(A8[2]),
        __float_as_uint(A8[3]), __float_as_uint(A8[4]), __float_as_uint(A8[5]),
        __float_as_uint(A8[6]), __float_as_uint(A8[7]),
        __float_as_uint(A2.x),  __float_as_uint(A2.y)};
    unsigned int bu[HP] = {
        __float_as_uint(B8[0]), __float_as_uint(B8[1]), __float_as_uint(B8[2]),
        __float_as_uint(B8[3]), __float_as_uint(B8[4]), __float_as_uint(B8[5]),
        __float_as_uint(B8[6]), __float_as_uint(B8[7]),
        __float_as_uint(B2.x),  __float_as_uint(B2.y)};

    unsigned int mh[HP];
#pragma unroll
    for (int p = 0; p < HP; p++) {
        float2 c = unpack2(acc[p]);
        float2 fa = h2f2(au[p]);
        float2 fb = h2f2(bu[p]);
        float2 mm;
        mm.x = fmaxf(c.x + fa.x + fb.x, 0.f);
        mm.y = fmaxf(c.y + fa.y + fb.y, 0.f);
        __half2 h = __float22half2_rn(mm);
        mh[p] = *(unsigned int*)&h;
    }

    char* xr = (char*)g_x + (size_t)dst * 64;
    asm volatile("red.global.add.noftz.v4.f16x2 [%0], {%1,%2,%3,%4};"
                 :: "l"(xr), "r"(mh[0]), "r"(mh[1]), "r"(mh[2]), "r"(mh[3]) : "memory");
    asm volatile("red.global.add.noftz.v4.f16x2 [%0], {%1,%2,%3,%4};"
                 :: "l"(xr + 16), "r"(mh[4]), "r"(mh[5]), "r"(mh[6]), "r"(mh[7]) : "memory");
    asm volatile("red.global.add.noftz.v2.f16x2 [%0], {%1,%2};"
                 :: "l"(xr + 32), "r"(mh[8]), "r"(mh[9]) : "memory");
}

// ---------------------------------------------------------------------------
// Kernel 3: node MLP + graph pooling (PDL consumer of edge_kernel)
// ---------------------------------------------------------------------------
__global__ __launch_bounds__(128) void node_mlp_kernel(
        const int*   __restrict__ batch,
        const float* __restrict__ W1,
        const float* __restrict__ b1) {
    __shared__ __align__(8) float sW[HID * H2];
    __shared__ __align__(8) float sb[H2];
    for (int i = threadIdx.x; i < HID * H2; i += blockDim.x) sW[i] = W1[i];
    for (int i = threadIdx.x; i < H2; i += blockDim.x) sb[i] = b1[i];
    __syncthreads();
    const unsigned long long* w2 = (const unsigned long long*)sW;
    const unsigned long long* sb2 = (const unsigned long long*)sb;

    int n = blockIdx.x * blockDim.x + threadIdx.x;
    if (n >= N_NODES) {
        cudaGridDependencySynchronize();
        return;
    }

    int b = __ldg(batch + n);     // input, safe before sync

    cudaGridDependencySynchronize();   // wait for edge_kernel's g_x

    const char* xrow = (const char*)g_x + (size_t)n * 64;
    float X8[8];
    ldg256(xrow, X8);
    float2 X2 = ldg64(xrow + 32);
    unsigned int xu[HP] = {
        __float_as_uint(X8[0]), __float_as_uint(X8[1]), __float_as_uint(X8[2]),
        __float_as_uint(X8[3]), __float_as_uint(X8[4]), __float_as_uint(X8[5]),
        __float_as_uint(X8[6]), __float_as_uint(X8[7]),
        __float_as_uint(X2.x),  __float_as_uint(X2.y)};

    float x[HID];
#pragma unroll
    for (int p = 0; p < HP; p++) {
        float2 t = h2f2(xu[p]);
        x[2*p] = t.x; x[2*p+1] = t.y;
    }

    unsigned long long acc[H2P];
#pragma unroll
    for (int p = 0; p < H2P; p++) acc[p] = sb2[p];
#pragma unroll
    for (int k = 0; k < HID; k++) {
        unsigned long long xk = bcast2(x[k]);
#pragma unroll
        for (int p = 0; p < H2P; p++) acc[p] = fma2(xk, w2[k * H2P + p], acc[p]);
    }

    float y[H2];
#pragma unroll
    for (int p = 0; p < H2P; p++) {
        float2 t = unpack2(acc[p]);
        y[2*p]   = fmaxf(t.x, 0.f);
        y[2*p+1] = fmaxf(t.y, 0.f);
    }

    float* gr = g_g + (size_t)b * H2;
#pragma unroll
    for (int q = 0; q < 5; q++) {
        asm volatile("red.global.add.v2.f32 [%0], {%1,%2};"
                     :: "l"(gr + 2*q), "f"(y[2*q]), "f"(y[2*q+1])
                     : "memory");
    }
}

// ---------------------------------------------------------------------------
// Kernel 4: graph MLP (PDL consumer of node_mlp)
// ---------------------------------------------------------------------------
__global__ __launch_bounds__(256) void graph_mlp_kernel(
        const float* __restrict__ W2,
        const float* __restrict__ b2,
        const float* __restrict__ W3,
        const float* __restrict__ b3,
        float* __restrict__ out) {
    __shared__ float sW2[H2 * H2];
    __shared__ float sb2[H2];
    __shared__ float sW3[H2];
    __shared__ float sb3;
    for (int i = threadIdx.x; i < H2 * H2; i += blockDim.x) sW2[i] = W2[i];
    if (threadIdx.x < H2) { sb2[threadIdx.x] = b2[threadIdx.x]; sW3[threadIdx.x] = W3[threadIdx.x]; }
    if (threadIdx.x == 0) sb3 = b3[0];
    __syncthreads();

    cudaGridDependencySynchronize();   // wait for node_mlp's g_g

    int g = blockIdx.x * blockDim.x + threadIdx.x;
    if (g >= N_GRAPHS) return;

    float v[H2];
    const float2* gp = (const float2*)(g_g + (size_t)g * H2);
#pragma unroll
    for (int q = 0; q < 5; q++) {
        float2 t = gp[q];
        v[2*q] = t.x; v[2*q+1] = t.y;
    }

    float o = sb3;
#pragma unroll
    for (int j = 0; j < H2; j++) {
        float h = sb2[j];
#pragma unroll
        for (int k = 0; k < H2; k++) h = fmaf(v[k], sW2[k * H2 + j], h);
        o = fmaf(fmaxf(h, 0.f), sW3[j], o);
    }
    out[g] = o;
}

// ---------------------------------------------------------------------------
extern "C" void kernel_launch(void* const* d_in, const int* in_sizes, int n_in,
                              void* d_out, int out_size) {
    const int*   edge_index = (const int*)  d_in[0];
    const float* node_attr  = (const float*)d_in[1];
    const float* edge_attr  = (const float*)d_in[2];
    const int*   batch      = (const int*)  d_in[3];
    const float* W_msg      = (const float*)d_in[4];
    const float* b_msg      = (const float*)d_in[5];
    const float* W1         = (const float*)d_in[6];
    const float* b1         = (const float*)d_in[7];
    const float* W2         = (const float*)d_in[8];
    const float* b2         = (const float*)d_in[9];
    const float* W3         = (const float*)d_in[10];
    const float* b3         = (const float*)d_in[11];
    float* out = (float*)d_out;

    // plain launch for the first kernel
    node_proj_kernel<<<(N_NODES + 127) / 128, 128>>>(node_attr, W_msg);

    // PDL launches for the dependent chain
    cudaLaunchAttribute attr[1];
    attr[0].id = cudaLaunchAttributeProgrammaticStreamSerialization;
    attr[0].val.programmaticStreamSerializationAllowed = 1;

    {
        cudaLaunchConfig_t cfg = {};
        cfg.gridDim  = dim3((N_EDGES + 255) / 256);
        cfg.blockDim = dim3(256);
        cfg.attrs = attr; cfg.numAttrs = 1;
        cudaLaunchKernelEx(&cfg, edge_kernel, edge_index, edge_attr, W_msg, b_msg);
    }
    {
        cudaLaunchConfig_t cfg = {};
        cfg.gridDim  = dim3((N_NODES + 127) / 128);
        cfg.blockDim = dim3(128);
        cfg.attrs = attr; cfg.numAttrs = 1;
        cudaLaunchKernelEx(&cfg, node_mlp_kernel, batch, W1, b1);
    }
    {
        cudaLaunchConfig_t cfg = {};
        cfg.gridDim  = dim3((N_GRAPHS + 255) / 256);
        cfg.blockDim = dim3(256);
        cfg.attrs = attr; cfg.numAttrs = 1;
        cudaLaunchKernelEx(&cfg, graph_mlp_kernel, W2, b2, W3, b3, out);
    }
}